// round 10
// baseline (speedup 1.0000x reference)
#include <cuda_runtime.h>
#include <cstdint>

#define BB 8
#define NN 128
#define KK 16
#define NB (BB*NN)
#define JSPLIT 32
#define JC 4                 // j's per warp in pairA

#define ALPHA_C 0.01f
#define LAM_C   1.0f
#define KAPPA_C 1.0f
#define EPSV    1e-6f

// scratch (device globals: no allocation allowed)
__device__ float g_E[NB * 256];          // E[bn] = expm(phi.G), row-major
__device__ float g_M[NB * 256];          // M[bn] = F diag(1/(sq+eps)) F^T (symmetric)
__device__ float g_w[NB * KK];           // w = F mu_q
__device__ float g_u[NB * KK];           // u = M w
__device__ float g_s1[JSPLIT * NB * KK]; // [split][bn][k]
__device__ float g_s2[JSPLIT * NB * KK];
__device__ float g_s3[JSPLIT * NB];

// ---------------------------------------------------------------------------
// 16x16 matmul step for 128-thread-per-matrix layout: thread = (i = t>>3,
// jd = t&7), owns C[i][jd*2], C[i][jd*2+1]. Both operands in smem.
// T row reads: 4-way broadcast; B reads: LDS.64 conflict-free.
// ---------------------------------------------------------------------------
__device__ __forceinline__ float2 mm2(const float* __restrict__ Ts,
                                      const float* __restrict__ Bs,
                                      int i, int jd)
{
    float c0 = 0.f, c1 = 0.f;
    #pragma unroll
    for (int l = 0; l < 16; l++) {
        const float t  = Ts[i*16 + l];
        const float2 b = *reinterpret_cast<const float2*>(Bs + l*16 + jd*2);
        c0 = fmaf(t, b.x, c0);
        c1 = fmaf(t, b.y, c1);
    }
    return make_float2(c0, c1);
}

// ---------------------------------------------------------------------------
// Kernel 1: one matrix per 128-thread block (1024 blocks).
// expm via Paterson-Stockmeyer Taylor-13; scaling count sc from the 2-norm
// estimate sqrt(||A^2||_inf); then E, M, w, u, grad_sigma.
// ---------------------------------------------------------------------------
__global__ void __launch_bounds__(128) prep_kernel(
    const float* __restrict__ mu_q,
    const float* __restrict__ sigma_q,
    const float* __restrict__ sigma_p,
    const float* __restrict__ phi,
    const float* __restrict__ gen,
    float* __restrict__ out_sigma)
{
    const int t  = threadIdx.x;
    const int i  = t >> 3;     // row 0..15
    const int jd = t & 7;      // col pair 0..7
    const int bn = blockIdx.x;
    const int base = i*16 + jd*2;

    __shared__ float bA[256], bX[256], bX2[256], bX3[256], bT[256];
    __shared__ float sr[16], smu[16], srm[16], srow[16];

    // ---- A = phi . G (this thread's 2 elements) ----
    const float p0 = __ldg(&phi[bn*3 + 0]);
    const float p1 = __ldg(&phi[bn*3 + 1]);
    const float p2 = __ldg(&phi[bn*3 + 2]);
    float a0 = p0*__ldg(&gen[base])   + p1*__ldg(&gen[256+base])   + p2*__ldg(&gen[512+base]);
    float a1 = p0*__ldg(&gen[base+1]) + p1*__ldg(&gen[256+base+1]) + p2*__ldg(&gen[512+base+1]);

    if (t < 16) {
        const float mu = mu_q[bn*KK + t];
        const float sq = fmaxf(sigma_q[bn*KK + t], EPSV);
        const float sp = fmaxf(sigma_p[bn*KK + t], EPSV);
        const float r  = 1.0f / (sq + EPSV);
        sr[t]  = r;
        smu[t] = mu;
        srm[t] = r * mu;
        out_sigma[bn*KK + t] = ALPHA_C * 0.5f * (1.0f/sp - 1.0f/sq);
    }

    bA[base] = a0; bA[base+1] = a1;
    __syncthreads();

    // ---- Xr = A^2 (unscaled); row inf-norm of Xr estimates ||A||_2^2 ----
    float2 xr = mm2(bA, bA, i, jd);
    float rs = fabsf(xr.x) + fabsf(xr.y);
    rs += __shfl_xor_sync(0xffffffffu, rs, 1);
    rs += __shfl_xor_sync(0xffffffffu, rs, 2);
    rs += __shfl_xor_sync(0xffffffffu, rs, 4);   // sum over jd -> row sum
    if (jd == 0) srow[i] = rs;
    __syncthreads();

    float nX = 0.f;
    #pragma unroll
    for (int l = 0; l < 16; l++) nX = fmaxf(nX, srow[l]);

    // sc = ceil(log4(nX / theta^2)), theta = 2.0
    int sc = 0;
    float tt = nX * 0.25f;
    while (tt > 1.0f && sc < 12) { sc++; tt *= 0.25f; }

    const float sA = ldexpf(1.0f, -sc);
    const float sXc = sA * sA;
    a0 *= sA;  a1 *= sA;
    float x0 = xr.x * sXc, x1 = xr.y * sXc;

    bA[base] = a0; bA[base+1] = a1;
    bX[base] = x0; bX[base+1] = x1;
    __syncthreads();

    // ---- X2 = X*X, X3 = X2*X ----
    float2 x2 = mm2(bX, bX, i, jd);
    bX2[base] = x2.x; bX2[base+1] = x2.y;
    __syncthreads();
    float2 x3 = mm2(bX2, bX, i, jd);
    bX3[base] = x3.x; bX3[base+1] = x3.y;

    // Taylor-13 even/odd coefficients
    const float c1c = 1.f/2.f,      c2c = 1.f/24.f,      c3c = 1.f/720.f;
    const float c4c = 1.f/40320.f,  c5c = 1.f/3628800.f, c6c = 1.f/479001600.f;
    const float d1c = 1.f/6.f,      d2c = 1.f/120.f,     d3c = 1.f/5040.f;
    const float d4c = 1.f/362880.f, d5c = 1.f/39916800.f, d6c = 1.6059044e-10f; // 1/13!

    // diag ownership: (i,i) owned iff jd*2 <= i < jd*2+2
    const int  dq      = i - jd*2;
    const bool hasdiag = (dq == 0) || (dq == 1);

    // P bracket
    bT[base]   = fmaf(c4c, x0, fmaf(c5c, x2.x, c6c*x3.x));
    bT[base+1] = fmaf(c4c, x1, fmaf(c5c, x2.y, c6c*x3.y));
    __syncthreads();
    float2 pb = mm2(bX3, bT, i, jd);
    float P0 = fmaf(c1c, x0, fmaf(c2c, x2.x, fmaf(c3c, x3.x, pb.x)));
    float P1 = fmaf(c1c, x1, fmaf(c2c, x2.y, fmaf(c3c, x3.y, pb.y)));
    if (hasdiag) { if (dq == 0) P0 += 1.0f; else P1 += 1.0f; }

    // Q bracket
    __syncthreads();                       // P-bracket reads of bT done
    bT[base]   = fmaf(d4c, x0, fmaf(d5c, x2.x, d6c*x3.x));
    bT[base+1] = fmaf(d4c, x1, fmaf(d5c, x2.y, d6c*x3.y));
    __syncthreads();
    float2 qb = mm2(bX3, bT, i, jd);
    float Q0 = fmaf(d1c, x0, fmaf(d2c, x2.x, fmaf(d3c, x3.x, qb.x)));
    float Q1 = fmaf(d1c, x1, fmaf(d2c, x2.y, fmaf(d3c, x3.y, qb.y)));
    if (hasdiag) { if (dq == 0) Q0 += 1.0f; else Q1 += 1.0f; }

    __syncthreads();                       // Q-bracket reads of bT done
    bT[base] = Q0; bT[base+1] = Q1;
    __syncthreads();
    float2 aq = mm2(bA, bT, i, jd);        // A*Q
    float R0 = aq.x + P0;
    float R1 = aq.y + P1;

    // ---- squarings, ping-pong bX / bX2 (dead after X3) ----
    float* pp[2] = { bX, bX2 };
    int cur = 0;
    for (int q = 0; q < sc; q++) {
        pp[cur][base] = R0; pp[cur][base+1] = R1;
        __syncthreads();
        float2 rr = mm2(pp[cur], pp[cur], i, jd);
        R0 = rr.x; R1 = rr.y;
        cur ^= 1;
    }

    // ---- write E; re-stage E into bA for transposed access ----
    *reinterpret_cast<float2*>(g_E + (size_t)bn*256 + base) = make_float2(R0, R1);
    __syncthreads();                       // readers of bA (A*Q mm) done
    bA[base] = R0; bA[base+1] = R1;
    __syncthreads();

    // ---- M[i][jd*2+q] = sum_l E[l][i] r[l] E[l][jd*2+q] ----
    {
        float m0 = 0.f, m1 = 0.f;
        #pragma unroll
        for (int l = 0; l < 16; l++) {
            const float e = bA[l*16 + i] * sr[l];
            const float2 b = *reinterpret_cast<const float2*>(bA + l*16 + jd*2);
            m0 = fmaf(e, b.x, m0);
            m1 = fmaf(e, b.y, m1);
        }
        *reinterpret_cast<float2*>(g_M + (size_t)bn*256 + base) = make_float2(m0, m1);
    }

    // ---- w[k] = sum_l E[l][k] mu[l];  u[k] = sum_l E[l][k] r[l] mu[l] ----
    if (t < 16) {
        float wacc = 0.f, uacc = 0.f;
        #pragma unroll
        for (int l = 0; l < 16; l++) {
            const float e = bA[l*16 + t];
            wacc = fmaf(e, smu[l], wacc);
            uacc = fmaf(e, srm[l], uacc);
        }
        g_w[bn*KK + t] = wacc;
        g_u[bn*KK + t] = uacc;
    }
}

// ---------------------------------------------------------------------------
// Kernel 2: warp-autonomous partial j-sums. Warp = (rowgroup of 32 rows,
// split of JC consecutive j's). lane = row. Everything per-pair is in-thread:
// y = M_j w_i (M rows via broadcast LDG.128), kl = d.y in-thread, no shfl,
// no smem, no barriers.
// ---------------------------------------------------------------------------
__global__ void __launch_bounds__(128) pairA_kernel(
    const float* __restrict__ beta)
{
    const int lane  = threadIdx.x & 31;
    const int gw    = blockIdx.x * 4 + (threadIdx.x >> 5);
    const int split = gw & (JSPLIT - 1);      // 0..31
    const int rg    = gw >> 5;                // 0..31 (NB/32 rowgroups)
    const int bn    = rg * 32 + lane;
    const int b     = bn >> 7;
    const int irow  = bn & 127;
    const int j0    = split * JC;

    // w_i in registers
    float wi[16];
    {
        const float4* wp = reinterpret_cast<const float4*>(g_w + (size_t)bn * KK);
        #pragma unroll
        for (int q = 0; q < 4; q++) {
            const float4 v = wp[q];
            wi[q*4+0] = v.x; wi[q*4+1] = v.y; wi[q*4+2] = v.z; wi[q*4+3] = v.w;
        }
    }

    const float* __restrict__ Mbase  = g_M + (size_t)(b*NN + j0) * 256;
    const float* __restrict__ wjbase = g_w + (size_t)(b*NN + j0) * KK;
    const float* __restrict__ ujbase = g_u + (size_t)(b*NN + j0) * KK;
    const float* __restrict__ brow   = beta + (size_t)(b*NN + irow) * NN + j0;

    float s1[16], s2[16];
    #pragma unroll
    for (int k = 0; k < 16; k++) { s1[k] = 0.f; s2[k] = 0.f; }
    float s3 = 0.f;

    #pragma unroll
    for (int jj = 0; jj < JC; jj++) {
        const float* __restrict__ M = Mbase + jj*256;

        // y = M w_i  (use symmetry: iterate rows l, broadcast reads)
        float y[16];
        #pragma unroll
        for (int k = 0; k < 16; k++) y[k] = 0.f;
        #pragma unroll
        for (int l = 0; l < 16; l++) {
            const float4 r0 = __ldg(reinterpret_cast<const float4*>(M + l*16));
            const float4 r1 = __ldg(reinterpret_cast<const float4*>(M + l*16 + 4));
            const float4 r2 = __ldg(reinterpret_cast<const float4*>(M + l*16 + 8));
            const float4 r3 = __ldg(reinterpret_cast<const float4*>(M + l*16 + 12));
            const float wl = wi[l];
            y[0]  = fmaf(r0.x, wl, y[0]);  y[1]  = fmaf(r0.y, wl, y[1]);
            y[2]  = fmaf(r0.z, wl, y[2]);  y[3]  = fmaf(r0.w, wl, y[3]);
            y[4]  = fmaf(r1.x, wl, y[4]);  y[5]  = fmaf(r1.y, wl, y[5]);
            y[6]  = fmaf(r1.z, wl, y[6]);  y[7]  = fmaf(r1.w, wl, y[7]);
            y[8]  = fmaf(r2.x, wl, y[8]);  y[9]  = fmaf(r2.y, wl, y[9]);
            y[10] = fmaf(r2.z, wl, y[10]); y[11] = fmaf(r2.w, wl, y[11]);
            y[12] = fmaf(r3.x, wl, y[12]); y[13] = fmaf(r3.y, wl, y[13]);
            y[14] = fmaf(r3.z, wl, y[14]); y[15] = fmaf(r3.w, wl, y[15]);
        }

        // y -= u_j ; build w_j, kl = 0.5 * sum_k (wi_k - wj_k) y_k
        float wj[16];
        {
            const float4* up = reinterpret_cast<const float4*>(ujbase + jj*KK);
            const float4* wp = reinterpret_cast<const float4*>(wjbase + jj*KK);
            #pragma unroll
            for (int q = 0; q < 4; q++) {
                const float4 u = __ldg(up + q);
                const float4 w = __ldg(wp + q);
                y[q*4+0] -= u.x; y[q*4+1] -= u.y; y[q*4+2] -= u.z; y[q*4+3] -= u.w;
                wj[q*4+0] = w.x; wj[q*4+1] = w.y; wj[q*4+2] = w.z; wj[q*4+3] = w.w;
            }
        }
        float kl = 0.f;
        #pragma unroll
        for (int k = 0; k < 16; k++) kl = fmaf(wi[k] - wj[k], y[k], kl);
        kl *= 0.5f;

        const float bij = __ldg(brow + jj);
        const float klb = kl * bij;
        #pragma unroll
        for (int k = 0; k < 16; k++) {
            s1[k] = fmaf(bij, y[k], s1[k]);
            s2[k] = fmaf(klb, y[k], s2[k]);
        }
        s3 += klb;
    }

    // store partials (each lane has its own bn)
    {
        float4* p1 = reinterpret_cast<float4*>(g_s1 + ((size_t)split*NB + bn)*KK);
        float4* p2 = reinterpret_cast<float4*>(g_s2 + ((size_t)split*NB + bn)*KK);
        #pragma unroll
        for (int q = 0; q < 4; q++) {
            p1[q] = make_float4(s1[q*4+0], s1[q*4+1], s1[q*4+2], s1[q*4+3]);
            p2[q] = make_float4(s2[q*4+0], s2[q*4+1], s2[q*4+2], s2[q*4+3]);
        }
        g_s3[split*NB + bn] = s3;
    }
}

// ---------------------------------------------------------------------------
// Kernel 3: combine splits, rotate by E_i, add self term.
// ---------------------------------------------------------------------------
__global__ void __launch_bounds__(256) finish_kernel(
    const float* __restrict__ mu_q,
    const float* __restrict__ mu_p,
    const float* __restrict__ sigma_p,
    float* __restrict__ out_mu)
{
    const int tid  = threadIdx.x;
    const int g    = tid >> 4;
    const int lane = tid & 15;
    const int bn   = blockIdx.x * 16 + g;

    float s1 = 0.f, s2 = 0.f, s3 = 0.f;
    #pragma unroll
    for (int s = 0; s < JSPLIT; s++) {
        s1 += g_s1[((size_t)s*NB + bn)*KK + lane];
        s2 += g_s2[((size_t)s*NB + bn)*KK + lane];
        s3 += g_s3[s*NB + bn];
    }
    const float v = LAM_C * s1 + (LAM_C / KAPPA_C) * (s2 - s3 * s1);

    float er[16];
    {
        const float4* ep = reinterpret_cast<const float4*>(g_E + (size_t)bn*256 + lane*16);
        #pragma unroll
        for (int q = 0; q < 4; q++) {
            const float4 t4 = ep[q];
            er[q*4+0] = t4.x; er[q*4+1] = t4.y; er[q*4+2] = t4.z; er[q*4+3] = t4.w;
        }
    }
    float o = 0.f;
    #pragma unroll
    for (int l = 0; l < 16; l++)
        o = fmaf(er[l], __shfl_sync(0xffffffffu, v, l, 16), o);

    const float sp   = fmaxf(sigma_p[bn*KK + lane], EPSV);
    const float self = ALPHA_C * (mu_q[bn*KK + lane] - mu_p[bn*KK + lane]) / sp;

    out_mu[bn*KK + lane] = self + o;
}

// ---------------------------------------------------------------------------
extern "C" void kernel_launch(void* const* d_in, const int* in_sizes, int n_in,
                              void* d_out, int out_size)
{
    const float* mu_q    = (const float*)d_in[0];
    const float* sigma_q = (const float*)d_in[1];
    const float* mu_p    = (const float*)d_in[2];
    const float* sigma_p = (const float*)d_in[3];
    const float* beta    = (const float*)d_in[4];
    const float* phi     = (const float*)d_in[5];
    const float* gen     = (const float*)d_in[6];

    float* out       = (float*)d_out;
    float* out_mu    = out;            // (B,N,K)
    float* out_sigma = out + NB*KK;    // (B,N,K)

    prep_kernel<<<NB, 128>>>(mu_q, sigma_q, sigma_p, phi, gen, out_sigma);
    pairA_kernel<<<(NB/32)*JSPLIT/4, 128>>>(beta);
    finish_kernel<<<NB/16, 256>>>(mu_q, mu_p, sigma_p, out_mu);
}